// round 4
// baseline (speedup 1.0000x reference)
#include <cuda_runtime.h>
#include <math.h>
#include <stdint.h>

#define TSTEPS  20
#define NLAYERS 4
#define DM      512
#define DS      128
#define ROWS    2048      // BATCH(4) * SEQ(512)
#define VOCAB   32000

// ---------------- scratch (device globals; no allocations allowed) ----------
__device__ uint32_t g_bits[2][TSTEPS][ROWS][16];   // spike bitmasks per layer boundary
__device__ float    g_AT[NLAYERS][DS * DS];        // AT[j*DS+i] = A[i][j]
__device__ float    g_BT[NLAYERS][DM * DS];        // BT[d*DS+i] = B[i][d]
__device__ float    g_CT[NLAYERS][DS * DM];        // CT[i*DM+d] = C[d][i]
__device__ float    g_cnt[ROWS * DM];              // (spike count)/20 of final layer

// ---------------- weight transposes ----------------------------------------
__global__ void prep_kernel(const float* __restrict__ A,
                            const float* __restrict__ Bm,
                            const float* __restrict__ Cm) {
    int stride = gridDim.x * blockDim.x;
    int gid = blockIdx.x * blockDim.x + threadIdx.x;
    for (int idx = gid; idx < NLAYERS * DS * DS; idx += stride) {
        int l = idx / (DS * DS); int rm = idx % (DS * DS);
        int i = rm / DS, j = rm % DS;
        g_AT[l][j * DS + i] = A[idx];
    }
    for (int idx = gid; idx < NLAYERS * DS * DM; idx += stride) {
        int l = idx / (DS * DM); int rm = idx % (DS * DM);
        int i = rm / DM, d = rm % DM;
        g_BT[l][d * DS + i] = Bm[idx];
    }
    for (int idx = gid; idx < NLAYERS * DM * DS; idx += stride) {
        int l = idx / (DM * DS); int rm = idx % (DM * DS);
        int d = rm / DS, i = rm % DS;
        g_CT[l][i * DM + d] = Cm[idx];
    }
}

__global__ void zero_bits_kernel() {
    int gid = blockIdx.x * blockDim.x + threadIdx.x;
    uint32_t* p = &g_bits[0][0][0][0];
    int n = TSTEPS * ROWS * 16;
    for (int i = gid; i < n; i += gridDim.x * blockDim.x) p[i] = 0u;
}

// ---------------- temporal encoding: one-hot over T as bitmasks -------------
// XLA's logistic lowers to 1/(1+exp(-x)) with libdevice expf; replicate that
// exact fp32 sequence (no branch, no double) so bins match bitwise.
__global__ void encode_kernel(const int* __restrict__ ids,
                              const float* __restrict__ emb) {
    int gid = blockIdx.x * blockDim.x + threadIdx.x;
    if (gid >= ROWS * DM) return;
    int r = gid >> 9, d = gid & (DM - 1);
    float x = emb[(long long)ids[r] * DM + d];
    float sgf = 1.0f / (1.0f + expf(-x));
    int t = (int)floorf(sgf * 19.0f);
    if (t < 0) t = 0;
    if (t > 19) t = 19;
    atomicOr(&g_bits[0][t][r][d >> 5], 1u << (d & 31));
}

// ---------------- one LIF-SSM layer: one CTA per (b,s) row ------------------
// Bit-sparse ascending-order gathers. Skipped zero terms are exact, so each
// sparse sum is bitwise identical to a dense ascending-k fp32 accumulation —
// the order used by cuBLAS/Eigen/XLA dots. The two dots of state_update are
// rounded separately and added once, mirroring round(h@A^T) + round(x@B^T).
__global__ __launch_bounds__(128) void ssm_kernel(int layer, int inb, int outb,
                                                  const float* __restrict__ Dfull) {
    int r   = blockIdx.x;
    int tid = threadIdx.x;
    int lane = tid & 31, wp = tid >> 5;
    const float* __restrict__ AT = g_AT[layer];
    const float* __restrict__ BT = g_BT[layer];
    const float* __restrict__ CT = g_CT[layer];
    const float* __restrict__ Dv = Dfull + layer * DM;

    __shared__ uint32_t sh_h[4];    // 128 state-spike bits
    __shared__ uint32_t sh_x[16];   // 512 input-spike bits

    float v1 = 0.f;                          // membrane of LIF1, state dim = tid
    float v2[4] = {0.f, 0.f, 0.f, 0.f};      // membrane of LIF2, dims tid+128k
    if (tid < 4) sh_h[tid] = 0u;

    for (int t = 0; t < TSTEPS; t++) {
        __syncthreads();                       // prior iter done with sh_x
        if (tid < 16) sh_x[tid] = g_bits[inb][t][r][tid];
        __syncthreads();

        // ---- state_update = h @ A^T + x_t @ B^T  (thread tid = state i) ----
        float sa = 0.f;
        #pragma unroll
        for (int w = 0; w < 4; w++) {
            uint32_t word = sh_h[w];
            while (word) {
                int j = __ffs(word) - 1; word &= word - 1;
                sa += AT[(w * 32 + j) * DS + tid];
            }
        }
        float sb = 0.f;
        #pragma unroll
        for (int w = 0; w < 16; w++) {
            uint32_t word = sh_x[w];
            while (word) {
                int b = __ffs(word) - 1; word &= word - 1;
                sb += BT[(w * 32 + b) * DS + tid];
            }
        }
        float u = sa + sb;                     // single add, like ref's M1 + M2
        // ---- LIF1: v += (u - v)/2; spike; hard reset ----
        v1 = v1 + (u - v1) * 0.5f;
        int s1 = (v1 - 1.0f) >= 0.f;
        uint32_t hb = __ballot_sync(0xffffffffu, s1);
        if (s1) v1 = 0.f;
        __syncthreads();                       // everyone done reading old sh_h
        if (lane == 0) sh_h[wp] = hb;
        __syncthreads();

        // ---- output_update = h_new @ C^T + x_t * D  (dims tid + 128k) ----
        float sc0 = 0.f, sc1 = 0.f, sc2 = 0.f, sc3 = 0.f;
        #pragma unroll
        for (int w = 0; w < 4; w++) {
            uint32_t word = sh_h[w];
            while (word) {
                int i2 = __ffs(word) - 1; word &= word - 1;
                const float* crow = CT + (w * 32 + i2) * DM + tid;
                sc0 += crow[0];
                sc1 += crow[128];
                sc2 += crow[256];
                sc3 += crow[384];
            }
        }
        float sc[4] = {sc0, sc1, sc2, sc3};
        #pragma unroll
        for (int k = 0; k < 4; k++) {
            float u2 = sc[k];
            if ((sh_x[4 * k + wp] >> lane) & 1u) u2 = u2 + Dv[tid + 128 * k];
            v2[k] = v2[k] + (u2 - v2[k]) * 0.5f;
            int s2 = (v2[k] - 1.0f) >= 0.f;
            uint32_t ob = __ballot_sync(0xffffffffu, s2);
            if (s2) v2[k] = 0.f;
            if (lane == 0) g_bits[outb][t][r][4 * k + wp] = ob;
        }
    }
}

// ---------------- spike counts over T, pre-divided by 20 --------------------
// Dividing here (c / 20.0f) makes every GEMM product term bit-identical to the
// reference's (mean first, then matmul).
__global__ void count_kernel() {
    int gid = blockIdx.x * blockDim.x + threadIdx.x;
    if (gid >= ROWS * DM) return;
    int r = gid >> 9, d = gid & (DM - 1);
    int w = d >> 5, b = d & 31;
    int c = 0;
    #pragma unroll
    for (int t = 0; t < TSTEPS; t++) c += (g_bits[0][t][r][w] >> b) & 1u;
    g_cnt[gid] = (float)c / 20.0f;
}

// ---------------- logits = ti @ Wp^T + bp -----------------------------------
// 128x128 block tile, 16 K-slab, 8x8 per thread, fp32 FMA, ascending k.
#define GBM 128
#define GBN 128
#define GBK 16
__global__ __launch_bounds__(256) void gemm_kernel(const float* __restrict__ Wp,
                                                   const float* __restrict__ bp,
                                                   float* __restrict__ out) {
    __shared__ float As[GBK * GBM];
    __shared__ float Bs[GBK * GBN];
    int bm = blockIdx.x, bn = blockIdx.y;   // bm fastest -> Wp tiles shared in L2
    int tid = threadIdx.x;
    int tx = tid & 15, ty = tid >> 4;
    const float* cbase = g_cnt + bm * GBM * DM;
    const float* wbase = Wp + (long long)bn * GBN * DM;

    float acc[8][8];
    #pragma unroll
    for (int i = 0; i < 8; i++)
        #pragma unroll
        for (int j = 0; j < 8; j++) acc[i][j] = 0.f;

    for (int k0 = 0; k0 < DM; k0 += GBK) {
        #pragma unroll
        for (int it = 0; it < 2; it++) {
            int f = tid + 256 * it;          // 0..511 float4 slots
            int row = f >> 2, c = f & 3;
            float4 va = *(const float4*)(cbase + row * DM + k0 + 4 * c);
            float4 vb = *(const float4*)(wbase + row * DM + k0 + 4 * c);
            As[(4 * c + 0) * GBM + row] = va.x;
            As[(4 * c + 1) * GBM + row] = va.y;
            As[(4 * c + 2) * GBM + row] = va.z;
            As[(4 * c + 3) * GBM + row] = va.w;
            Bs[(4 * c + 0) * GBN + row] = vb.x;
            Bs[(4 * c + 1) * GBN + row] = vb.y;
            Bs[(4 * c + 2) * GBN + row] = vb.z;
            Bs[(4 * c + 3) * GBN + row] = vb.w;
        }
        __syncthreads();
        #pragma unroll
        for (int k = 0; k < GBK; k++) {
            float a[8], b[8];
            *(float4*)&a[0] = *(const float4*)&As[k * GBM + ty * 8];
            *(float4*)&a[4] = *(const float4*)&As[k * GBM + ty * 8 + 4];
            *(float4*)&b[0] = *(const float4*)&Bs[k * GBN + tx * 8];
            *(float4*)&b[4] = *(const float4*)&Bs[k * GBN + tx * 8 + 4];
            #pragma unroll
            for (int i = 0; i < 8; i++)
                #pragma unroll
                for (int j = 0; j < 8; j++) acc[i][j] += a[i] * b[j];
        }
        __syncthreads();
    }

    float bias[8];
    #pragma unroll
    for (int j = 0; j < 8; j++) bias[j] = bp[bn * GBN + tx * 8 + j];
    #pragma unroll
    for (int i = 0; i < 8; i++) {
        int rr = bm * GBM + ty * 8 + i;
        float* op = out + (long long)rr * VOCAB + bn * GBN + tx * 8;
        float4 o0, o1;
        o0.x = acc[i][0] + bias[0];
        o0.y = acc[i][1] + bias[1];
        o0.z = acc[i][2] + bias[2];
        o0.w = acc[i][3] + bias[3];
        o1.x = acc[i][4] + bias[4];
        o1.y = acc[i][5] + bias[5];
        o1.z = acc[i][6] + bias[6];
        o1.w = acc[i][7] + bias[7];
        *(float4*)(op)     = o0;
        *(float4*)(op + 4) = o1;
    }
}

// ---------------- launch -----------------------------------------------------
extern "C" void kernel_launch(void* const* d_in, const int* in_sizes, int n_in,
                              void* d_out, int out_size) {
    const int*   ids  = (const int*)d_in[0];
    const float* emb  = (const float*)d_in[1];
    const float* A    = (const float*)d_in[2];
    const float* Bm   = (const float*)d_in[3];
    const float* Cm   = (const float*)d_in[4];
    const float* Dm_  = (const float*)d_in[5];
    const float* Wp   = (const float*)d_in[6];
    const float* bp   = (const float*)d_in[7];
    float*       out  = (float*)d_out;

    prep_kernel<<<256, 256>>>(A, Bm, Cm);
    zero_bits_kernel<<<256, 256>>>();
    encode_kernel<<<(ROWS * DM + 255) / 256, 256>>>(ids, emb);

    // layer l reads buffer l&1, writes (l+1)&1; final spikes land in buffer 0
    ssm_kernel<<<ROWS, 128>>>(0, 0, 1, Dm_);
    ssm_kernel<<<ROWS, 128>>>(1, 1, 0, Dm_);
    ssm_kernel<<<ROWS, 128>>>(2, 0, 1, Dm_);
    ssm_kernel<<<ROWS, 128>>>(3, 1, 0, Dm_);

    count_kernel<<<(ROWS * DM + 255) / 256, 256>>>();
    gemm_kernel<<<dim3(ROWS / GBM, VOCAB / GBN), 256>>>(Wp, bp, out);
}

// round 5
// speedup vs baseline: 1.8854x; 1.8854x over previous
#include <cuda_runtime.h>
#include <cuda_bf16.h>
#include <math.h>
#include <stdint.h>

#define TSTEPS  20
#define NLAYERS 4
#define DM      512
#define DS      128
#define ROWS    2048      // BATCH(4) * SEQ(512)
#define VOCAB   32000

// ---------------- scratch (device globals; no allocations allowed) ----------
__device__ uint32_t      g_bits[2][TSTEPS][ROWS][16];
__device__ float         g_AT[NLAYERS][DS * DS];      // AT[j*DS+i] = A[i][j]
__device__ float         g_BT[NLAYERS][DM * DS];      // BT[d*DS+i] = B[i][d]
__device__ float         g_CT[NLAYERS][DS * DM];      // CT[i*DM+d] = C[d][i]
__device__ __nv_bfloat16 g_cntb[ROWS * DM];           // exact integer spike counts
__device__ __nv_bfloat16 g_wph[(size_t)VOCAB * DM];   // bf16 hi of Wp
__device__ __nv_bfloat16 g_wpl[(size_t)VOCAB * DM];   // bf16 lo of Wp

// ---------------- weight transposes ----------------------------------------
__global__ void prep_kernel(const float* __restrict__ A,
                            const float* __restrict__ Bm,
                            const float* __restrict__ Cm) {
    int stride = gridDim.x * blockDim.x;
    int gid = blockIdx.x * blockDim.x + threadIdx.x;
    for (int idx = gid; idx < NLAYERS * DS * DS; idx += stride) {
        int l = idx / (DS * DS); int rm = idx % (DS * DS);
        int i = rm / DS, j = rm % DS;
        g_AT[l][j * DS + i] = A[idx];
    }
    for (int idx = gid; idx < NLAYERS * DS * DM; idx += stride) {
        int l = idx / (DS * DM); int rm = idx % (DS * DM);
        int i = rm / DM, d = rm % DM;
        g_BT[l][d * DS + i] = Bm[idx];
    }
    for (int idx = gid; idx < NLAYERS * DM * DS; idx += stride) {
        int l = idx / (DM * DS); int rm = idx % (DM * DS);
        int d = rm / DS, i = rm % DS;
        g_CT[l][i * DM + d] = Cm[idx];
    }
}

// ---------------- Wp two-term bf16 split ------------------------------------
__global__ void split_wp_kernel(const float* __restrict__ Wp) {
    long long i = (long long)blockIdx.x * blockDim.x + threadIdx.x;
    if (i >= (long long)VOCAB * DM) return;
    float w = Wp[i];
    __nv_bfloat16 h = __float2bfloat16(w);
    g_wph[i] = h;
    g_wpl[i] = __float2bfloat16(w - __bfloat162float(h));
}

__global__ void zero_bits_kernel() {
    int gid = blockIdx.x * blockDim.x + threadIdx.x;
    uint32_t* p = &g_bits[0][0][0][0];
    int n = TSTEPS * ROWS * 16;
    for (int i = gid; i < n; i += gridDim.x * blockDim.x) p[i] = 0u;
}

// ---------------- temporal encoding (exact fp32 logistic, as validated) -----
__global__ void encode_kernel(const int* __restrict__ ids,
                              const float* __restrict__ emb) {
    int gid = blockIdx.x * blockDim.x + threadIdx.x;
    if (gid >= ROWS * DM) return;
    int r = gid >> 9, d = gid & (DM - 1);
    float x = emb[(long long)ids[r] * DM + d];
    float sgf = 1.0f / (1.0f + expf(-x));
    int t = (int)floorf(sgf * 19.0f);
    if (t < 0) t = 0;
    if (t > 19) t = 19;
    atomicOr(&g_bits[0][t][r][d >> 5], 1u << (d & 31));
}

// ---------------- one LIF-SSM layer: one CTA per (b,s) row ------------------
// Same ascending-order, single-accumulator-per-dot arithmetic as the validated
// round-4 kernel (bit-exact vs reference). Performance change only: bitmasks
// are first unpacked to ascending index lists in shared memory, so the gather
// loops have address streams independent of the accumulator chain -> the
// compiler batches loads (MLP) instead of exposing full load latency per term.
__global__ __launch_bounds__(128) void ssm_kernel(int layer, int inb, int outb,
                                                  const float* __restrict__ Dfull) {
    int r   = blockIdx.x;
    int tid = threadIdx.x;
    int lane = tid & 31, wp = tid >> 5;
    const float* __restrict__ AT = g_AT[layer];
    const float* __restrict__ BT = g_BT[layer];
    const float* __restrict__ CT = g_CT[layer];
    const float* __restrict__ Dv = Dfull + layer * DM;

    __shared__ uint32_t sh_x[16];
    __shared__ uint32_t sh_h[4];
    __shared__ int sh_xidx[512];   // x indices pre-multiplied by DS (B stride)
    __shared__ int sh_hidx[128];   // raw h indices
    __shared__ int sh_nx, sh_nh;

    float v1 = 0.f;
    float v2[4] = {0.f, 0.f, 0.f, 0.f};
    if (tid == 0) { sh_nh = 0; sh_nx = 0; }

    for (int t = 0; t < TSTEPS; t++) {
        __syncthreads();                       // prior iter done with sh_x lists
        if (tid < 16) sh_x[tid] = g_bits[inb][t][r][tid];
        __syncthreads();

        // unpack x bits -> ascending index list (16 lanes of warp 0)
        if (tid < 16) {
            uint32_t w = sh_x[tid];
            int c = __popc(w);
            int incl = c;
            #pragma unroll
            for (int off = 1; off < 16; off <<= 1) {
                int y = __shfl_up_sync(0xffffu, incl, off);
                if (tid >= off) incl += y;
            }
            int pos = incl - c;
            while (w) {
                int b = __ffs(w) - 1; w &= w - 1;
                sh_xidx[pos++] = ((tid << 5) + b) * DS;
            }
            if (tid == 15) sh_nx = incl;
        }
        __syncthreads();

        // ---- state_update = h @ A^T + x_t @ B^T (thread tid = state i) ----
        int nh = sh_nh, nx = sh_nx;
        float sa = 0.f;
        #pragma unroll 4
        for (int i = 0; i < nh; i++) sa += AT[sh_hidx[i] * DS + tid];
        float sb = 0.f;
        #pragma unroll 4
        for (int i = 0; i < nx; i++) sb += BT[sh_xidx[i] + tid];
        float u = sa + sb;                     // single add, like ref's M1 + M2

        // ---- LIF1 ----
        v1 = v1 + (u - v1) * 0.5f;
        int s1 = (v1 - 1.0f) >= 0.f;
        uint32_t hb = __ballot_sync(0xffffffffu, s1);
        if (s1) v1 = 0.f;
        __syncthreads();                       // old sh_h/sh_hidx consumed
        if (lane == 0) sh_h[wp] = hb;
        __syncthreads();

        // unpack new h bits (4 lanes of warp 0)
        if (tid < 4) {
            uint32_t w = sh_h[tid];
            int c = __popc(w);
            int incl = c;
            #pragma unroll
            for (int off = 1; off < 4; off <<= 1) {
                int y = __shfl_up_sync(0xfu, incl, off);
                if (tid >= off) incl += y;
            }
            int pos = incl - c;
            while (w) {
                int b = __ffs(w) - 1; w &= w - 1;
                sh_hidx[pos++] = (tid << 5) + b;
            }
            if (tid == 3) sh_nh = incl;
        }
        __syncthreads();

        // ---- output_update = h_new @ C^T + x_t * D  (dims tid + 128k) ----
        int nh2 = sh_nh;
        float sc0 = 0.f, sc1 = 0.f, sc2 = 0.f, sc3 = 0.f;
        #pragma unroll 2
        for (int i = 0; i < nh2; i++) {
            const float* crow = CT + sh_hidx[i] * DM + tid;
            sc0 += crow[0];
            sc1 += crow[128];
            sc2 += crow[256];
            sc3 += crow[384];
        }
        float sc[4] = {sc0, sc1, sc2, sc3};
        #pragma unroll
        for (int k = 0; k < 4; k++) {
            float u2 = sc[k];
            if ((sh_x[4 * k + wp] >> lane) & 1u) u2 = u2 + Dv[tid + 128 * k];
            v2[k] = v2[k] + (u2 - v2[k]) * 0.5f;
            int s2 = (v2[k] - 1.0f) >= 0.f;
            uint32_t ob = __ballot_sync(0xffffffffu, s2);
            if (s2) v2[k] = 0.f;
            if (lane == 0) g_bits[outb][t][r][4 * k + wp] = ob;
        }
    }
}

// ---------------- spike counts over T (exact small ints, bf16) --------------
__global__ void count_kernel() {
    int gid = blockIdx.x * blockDim.x + threadIdx.x;
    if (gid >= ROWS * DM) return;
    int r = gid >> 9, d = gid & (DM - 1);
    int w = d >> 5, b = d & 31;
    int c = 0;
    #pragma unroll
    for (int t = 0; t < TSTEPS; t++) c += (g_bits[0][t][r][w] >> b) & 1u;
    g_cntb[gid] = __float2bfloat16((float)c);   // integers <= 20: exact in bf16
}

// ---------------- logits = (cnt @ (hi+lo)^T) * 0.05 + bp --------------------
// Split-bf16 tensor-core GEMM: mma.sync.m16n8k16 (bf16 x bf16 -> f32 accum).
// Block tile 128x128, warps 2x4 (warp tile 64x32), K-slab 16, reg-prefetch
// pipeline over k. Smem tiles padded to 40 bf16/row for conflict-free frags.
#define SPAD 40
__device__ __forceinline__ void mma16816(float* d, const uint32_t* a, const uint32_t* b) {
    asm volatile(
        "mma.sync.aligned.m16n8k16.row.col.f32.bf16.bf16.f32 "
        "{%0,%1,%2,%3}, {%4,%5,%6,%7}, {%8,%9}, {%0,%1,%2,%3};"
        : "+f"(d[0]), "+f"(d[1]), "+f"(d[2]), "+f"(d[3])
        : "r"(a[0]), "r"(a[1]), "r"(a[2]), "r"(a[3]), "r"(b[0]), "r"(b[1]));
}

__global__ __launch_bounds__(256) void gemm_bf16_kernel(const float* __restrict__ bp,
                                                        float* __restrict__ out) {
    __shared__ __nv_bfloat16 s_a [128 * SPAD];
    __shared__ __nv_bfloat16 s_bh[128 * SPAD];
    __shared__ __nv_bfloat16 s_bl[128 * SPAD];

    int bm = blockIdx.x, bn = blockIdx.y;   // bm fastest -> Wp tiles reused in L2
    int tid = threadIdx.x;
    int w   = tid >> 5;
    int wm  = w >> 2, wn = w & 3;           // 2 x 4 warps
    int lane = tid & 31;
    int g = lane >> 2, tig = lane & 3;

    // global load mapping: 2 threads per row, 8 bf16 (16B) each
    int lrow = tid >> 1, lhalf = tid & 1;
    const __nv_bfloat16* a_src  = g_cntb + (size_t)(bm * 128 + lrow) * DM + lhalf * 8;
    const __nv_bfloat16* bh_src = g_wph  + (size_t)(bn * 128 + lrow) * DM + lhalf * 8;
    const __nv_bfloat16* bl_src = g_wpl  + (size_t)(bn * 128 + lrow) * DM + lhalf * 8;
    int sdst = lrow * SPAD + lhalf * 8;

    uint4 ra = *(const uint4*)a_src;
    uint4 rh = *(const uint4*)bh_src;
    uint4 rl = *(const uint4*)bl_src;

    float acc[4][4][4];
    #pragma unroll
    for (int i = 0; i < 4; i++)
        #pragma unroll
        for (int j = 0; j < 4; j++)
            #pragma unroll
            for (int q = 0; q < 4; q++) acc[i][j][q] = 0.f;

    for (int ks = 0; ks < DM / 16; ks++) {
        __syncthreads();
        *(uint4*)(s_a  + sdst) = ra;
        *(uint4*)(s_bh + sdst) = rh;
        *(uint4*)(s_bl + sdst) = rl;
        __syncthreads();
        if (ks < DM / 16 - 1) {
            ra = *(const uint4*)(a_src  + (ks + 1) * 16);
            rh = *(const uint4*)(bh_src + (ks + 1) * 16);
            rl = *(const uint4*)(bl_src + (ks + 1) * 16);
        }

        // A fragments for this warp's 4 m16 tiles
        uint32_t afr[4][4];
        #pragma unroll
        for (int mf = 0; mf < 4; mf++) {
            int m0 = wm * 64 + mf * 16;
            const __nv_bfloat16* base = s_a + (m0 + g) * SPAD + 2 * tig;
            afr[mf][0] = *(const uint32_t*)(base);
            afr[mf][1] = *(const uint32_t*)(base + 8 * SPAD);
            afr[mf][2] = *(const uint32_t*)(base + 8);
            afr[mf][3] = *(const uint32_t*)(base + 8 * SPAD + 8);
        }
        #pragma unroll
        for (int nf = 0; nf < 4; nf++) {
            int n0 = wn * 32 + nf * 8;
            const __nv_bfloat16* hb = s_bh + (n0 + g) * SPAD + 2 * tig;
            const __nv_bfloat16* lb = s_bl + (n0 + g) * SPAD + 2 * tig;
            uint32_t bh[2], bl[2];
            bh[0] = *(const uint32_t*)(hb);
            bh[1] = *(const uint32_t*)(hb + 8);
            bl[0] = *(const uint32_t*)(lb);
            bl[1] = *(const uint32_t*)(lb + 8);
            #pragma unroll
            for (int mf = 0; mf < 4; mf++) {
                mma16816(acc[mf][nf], afr[mf], bh);
                mma16816(acc[mf][nf], afr[mf], bl);
            }
        }
    }

    // epilogue: logits = acc * (1/20) + bias
    #pragma unroll
    for (int nf = 0; nf < 4; nf++) {
        int col = bn * 128 + wn * 32 + nf * 8 + 2 * tig;
        float2 bias = *(const float2*)(bp + col);
        #pragma unroll
        for (int mf = 0; mf < 4; mf++) {
            int row0 = bm * 128 + wm * 64 + mf * 16 + g;
            float2 o0, o1;
            o0.x = acc[mf][nf][0] * 0.05f + bias.x;
            o0.y = acc[mf][nf][1] * 0.05f + bias.y;
            o1.x = acc[mf][nf][2] * 0.05f + bias.x;
            o1.y = acc[mf][nf][3] * 0.05f + bias.y;
            *(float2*)(out + (size_t)row0 * VOCAB + col)       = o0;
            *(float2*)(out + (size_t)(row0 + 8) * VOCAB + col) = o1;
        }
    }
}

// ---------------- launch -----------------------------------------------------
extern "C" void kernel_launch(void* const* d_in, const int* in_sizes, int n_in,
                              void* d_out, int out_size) {
    const int*   ids  = (const int*)d_in[0];
    const float* emb  = (const float*)d_in[1];
    const float* A    = (const float*)d_in[2];
    const float* Bm   = (const float*)d_in[3];
    const float* Cm   = (const float*)d_in[4];
    const float* Dm_  = (const float*)d_in[5];
    const float* Wp   = (const float*)d_in[6];
    const float* bp   = (const float*)d_in[7];
    float*       out  = (float*)d_out;

    prep_kernel<<<256, 256>>>(A, Bm, Cm);
    split_wp_kernel<<<(VOCAB * DM + 255) / 256, 256>>>(Wp);
    zero_bits_kernel<<<256, 256>>>();
    encode_kernel<<<(ROWS * DM + 255) / 256, 256>>>(ids, emb);

    ssm_kernel<<<ROWS, 128>>>(0, 0, 1, Dm_);
    ssm_kernel<<<ROWS, 128>>>(1, 1, 0, Dm_);
    ssm_kernel<<<ROWS, 128>>>(2, 0, 1, Dm_);
    ssm_kernel<<<ROWS, 128>>>(3, 1, 0, Dm_);

    count_kernel<<<(ROWS * DM + 255) / 256, 256>>>();
    gemm_bf16_kernel<<<dim3(ROWS / 128, VOCAB / 128), 256>>>(bp, out);
}